// round 1
// baseline (speedup 1.0000x reference)
#include <cuda_runtime.h>
#include <cuda_bf16.h>
#include <math.h>

// Problem constants (fixed by the reference)
#define BATCH 4
#define SEQ   2048
#define DMODEL 1024
#define NHEAD 16
#define HDIM  64
#define MTOT  (BATCH*SEQ)          // 8192 rows for the projections

// ---------------------------------------------------------------------------
// Scratch (device globals: allocation-free per harness rules)
// ---------------------------------------------------------------------------
__device__ float g_q[BATCH*NHEAD*SEQ*HDIM];   // [B,H,S,HD]
__device__ float g_k[BATCH*NHEAD*SEQ*HDIM];
__device__ float g_v[BATCH*NHEAD*SEQ*HDIM];
__device__ float g_ctx[MTOT*DMODEL];          // [B,S,D]

// ---------------------------------------------------------------------------
// GEMM: C[m,n] = sum_k A[m,k] * W[n,k] + bias[n]      (NT, both K-major)
// MODE 0: C row-major [M,N]
// MODE 1: scatter to [B,H,S,HD] layout (n = h*HD+dd, m = b*SEQ+s)
// Tiles: BM=BN=128, BK=16, 256 threads, 8x8 microtile.
// ---------------------------------------------------------------------------
#define BM 128
#define BN 128
#define BK 16

template<int MODE>
__global__ void __launch_bounds__(256, 2)
gemm_nt(const float* __restrict__ A, const float* __restrict__ W,
        const float* __restrict__ bias, float* __restrict__ C,
        int M, int N, int K)
{
    __shared__ float As[BK][BM];
    __shared__ float Bs[BK][BN];

    const int tid = threadIdx.x;
    const int m0 = blockIdx.y * BM;
    const int n0 = blockIdx.x * BN;
    const int tm = tid >> 4;        // 0..15
    const int tn = tid & 15;        // 0..15

    float acc[8][8];
#pragma unroll
    for (int i = 0; i < 8; ++i)
#pragma unroll
        for (int j = 0; j < 8; ++j) acc[i][j] = 0.f;

    for (int kt = 0; kt < K; kt += BK) {
        // load A tile (128x16) and B tile (128x16), transposed into smem
#pragma unroll
        for (int t = tid; t < (BM*BK)/4; t += 256) {
            int row = t >> 2;
            int c4  = (t & 3) * 4;
            float4 av = *(const float4*)&A[(size_t)(m0+row)*K + kt + c4];
            As[c4+0][row] = av.x; As[c4+1][row] = av.y;
            As[c4+2][row] = av.z; As[c4+3][row] = av.w;
            float4 bv = *(const float4*)&W[(size_t)(n0+row)*K + kt + c4];
            Bs[c4+0][row] = bv.x; Bs[c4+1][row] = bv.y;
            Bs[c4+2][row] = bv.z; Bs[c4+3][row] = bv.w;
        }
        __syncthreads();

#pragma unroll
        for (int kk = 0; kk < BK; ++kk) {
            float4 a0 = *(const float4*)&As[kk][tm*8];
            float4 a1 = *(const float4*)&As[kk][tm*8+4];
            float4 b0 = *(const float4*)&Bs[kk][tn*8];
            float4 b1 = *(const float4*)&Bs[kk][tn*8+4];
            float ar[8] = {a0.x,a0.y,a0.z,a0.w,a1.x,a1.y,a1.z,a1.w};
            float br[8] = {b0.x,b0.y,b0.z,b0.w,b1.x,b1.y,b1.z,b1.w};
#pragma unroll
            for (int i = 0; i < 8; ++i)
#pragma unroll
                for (int j = 0; j < 8; ++j)
                    acc[i][j] += ar[i]*br[j];
        }
        __syncthreads();
    }

    // epilogue
#pragma unroll
    for (int i = 0; i < 8; ++i) {
        int mrow = m0 + tm*8 + i;
#pragma unroll
        for (int j = 0; j < 8; ++j) {
            int ncol = n0 + tn*8 + j;
            float val = acc[i][j] + bias[ncol];
            if (MODE == 0) {
                C[(size_t)mrow*N + ncol] = val;
            } else {
                int b  = mrow >> 11;            // / SEQ
                int s  = mrow & (SEQ-1);
                int h  = ncol >> 6;             // / HDIM
                int dd = ncol & (HDIM-1);
                C[(((size_t)(b*NHEAD + h))*SEQ + s)*HDIM + dd] = val;
            }
        }
    }
}

// ---------------------------------------------------------------------------
// RoPE (reference semantics: c = sin part, s = cos part!)
// out1 = x1*sin - x2*cos ; out2 = x2*sin + x1*cos
// ---------------------------------------------------------------------------
__global__ void rope_kernel(float* __restrict__ q, float* __restrict__ k)
{
    int idx = blockIdx.x*blockDim.x + threadIdx.x;  // over B*H*S*(HD/2)
    if (idx >= BATCH*NHEAD*SEQ*(HDIM/2)) return;
    int j  = idx & 31;
    int s  = (idx >> 5) & (SEQ-1);
    int bh = idx >> 16;                             // / (32*SEQ)

    float inv = powf(10000.f, -(float)j / 32.f);
    float ang = (float)s * inv;
    float sn, cs;
    sincosf(ang, &sn, &cs);

    size_t base = ((size_t)bh*SEQ + s)*HDIM;
    {
        float x1 = q[base+j], x2 = q[base+j+32];
        q[base+j]    = x1*sn - x2*cs;
        q[base+j+32] = x2*sn + x1*cs;
    }
    {
        float x1 = k[base+j], x2 = k[base+j+32];
        k[base+j]    = x1*sn - x2*cs;
        k[base+j+32] = x2*sn + x1*cs;
    }
}

// ---------------------------------------------------------------------------
// Flash attention, fp32. 64x64 Q/K tiles, HD=64. 256 threads, 4x4 microtiles.
// Dynamic smem: Qs(16K) + Ks(16K) + Vs(16K) + Ps(16K) = 64KB.
// ---------------------------------------------------------------------------
#define AQ 64
#define AK 64

__global__ void __launch_bounds__(256, 2)
attn_kernel(const float* __restrict__ Q, const float* __restrict__ Kb,
            const float* __restrict__ Vb, float* __restrict__ ctx)
{
    extern __shared__ float sm[];
    float* Qs = sm;                 // [AQ][HD]
    float* Ks = Qs + AQ*HDIM;       // [AK][HD]
    float* Vs = Ks + AK*HDIM;       // [AK][HD]
    float* Ps = Vs + AK*HDIM;       // [AQ][AK]

    const int tid = threadIdx.x;
    const int q0  = blockIdx.x * AQ;
    const int bh  = blockIdx.y;

    const float* qg = Q  + ((size_t)bh*SEQ + q0)*HDIM;
    const float* kg = Kb + (size_t)bh*SEQ*HDIM;
    const float* vg = Vb + (size_t)bh*SEQ*HDIM;

    // load Q tile once
#pragma unroll
    for (int t = tid; t < AQ*HDIM/4; t += 256)
        ((float4*)Qs)[t] = ((const float4*)qg)[t];

    const int tr = tid >> 4, tc = tid & 15;
    const int r0 = tr*4, c0 = tc*4;

    float m[4], l[4], o[4][4];
#pragma unroll
    for (int i = 0; i < 4; ++i) {
        m[i] = -INFINITY; l[i] = 0.f;
#pragma unroll
        for (int j = 0; j < 4; ++j) o[i][j] = 0.f;
    }
    __syncthreads();

    for (int k0 = 0; k0 < SEQ; k0 += AK) {
#pragma unroll
        for (int t = tid; t < AK*HDIM/4; t += 256) {
            ((float4*)Ks)[t] = ((const float4*)(kg + (size_t)k0*HDIM))[t];
            ((float4*)Vs)[t] = ((const float4*)(vg + (size_t)k0*HDIM))[t];
        }
        __syncthreads();

        // S = Q K^T
        float s[4][4];
#pragma unroll
        for (int i = 0; i < 4; ++i)
#pragma unroll
            for (int j = 0; j < 4; ++j) s[i][j] = 0.f;

#pragma unroll 4
        for (int d = 0; d < HDIM; d += 4) {
            float4 a[4], b[4];
#pragma unroll
            for (int i = 0; i < 4; ++i) a[i] = *(const float4*)&Qs[(r0+i)*HDIM + d];
#pragma unroll
            for (int j = 0; j < 4; ++j) b[j] = *(const float4*)&Ks[(c0+j)*HDIM + d];
#pragma unroll
            for (int i = 0; i < 4; ++i)
#pragma unroll
                for (int j = 0; j < 4; ++j)
                    s[i][j] += a[i].x*b[j].x + a[i].y*b[j].y + a[i].z*b[j].z + a[i].w*b[j].w;
        }

        // online softmax (scale = 1/sqrt(64) = 0.125)
#pragma unroll
        for (int i = 0; i < 4; ++i) {
            float mx = -INFINITY;
#pragma unroll
            for (int j = 0; j < 4; ++j) { s[i][j] *= 0.125f; mx = fmaxf(mx, s[i][j]); }
            mx = fmaxf(mx, __shfl_xor_sync(0xffffffffu, mx, 8));
            mx = fmaxf(mx, __shfl_xor_sync(0xffffffffu, mx, 4));
            mx = fmaxf(mx, __shfl_xor_sync(0xffffffffu, mx, 2));
            mx = fmaxf(mx, __shfl_xor_sync(0xffffffffu, mx, 1));
            float mn = fmaxf(m[i], mx);
            float al = expf(m[i] - mn);
            m[i] = mn;
            float rs = 0.f;
#pragma unroll
            for (int j = 0; j < 4; ++j) {
                float p = expf(s[i][j] - mn);
                Ps[(r0+i)*AK + c0 + j] = p;
                rs += p;
            }
            rs += __shfl_xor_sync(0xffffffffu, rs, 8);
            rs += __shfl_xor_sync(0xffffffffu, rs, 4);
            rs += __shfl_xor_sync(0xffffffffu, rs, 2);
            rs += __shfl_xor_sync(0xffffffffu, rs, 1);
            l[i] = l[i]*al + rs;
#pragma unroll
            for (int j = 0; j < 4; ++j) o[i][j] *= al;
        }
        __syncthreads();

        // O += P V
#pragma unroll 4
        for (int c = 0; c < AK; c += 4) {
            float4 pr[4];
#pragma unroll
            for (int i = 0; i < 4; ++i) pr[i] = *(const float4*)&Ps[(r0+i)*AK + c];
            float4 vv[4];
#pragma unroll
            for (int cc = 0; cc < 4; ++cc) vv[cc] = *(const float4*)&Vs[(c+cc)*HDIM + c0];
#pragma unroll
            for (int i = 0; i < 4; ++i) {
                o[i][0] += pr[i].x*vv[0].x + pr[i].y*vv[1].x + pr[i].z*vv[2].x + pr[i].w*vv[3].x;
                o[i][1] += pr[i].x*vv[0].y + pr[i].y*vv[1].y + pr[i].z*vv[2].y + pr[i].w*vv[3].y;
                o[i][2] += pr[i].x*vv[0].z + pr[i].y*vv[1].z + pr[i].z*vv[2].z + pr[i].w*vv[3].z;
                o[i][3] += pr[i].x*vv[0].w + pr[i].y*vv[1].w + pr[i].z*vv[2].w + pr[i].w*vv[3].w;
            }
        }
        __syncthreads();
    }

    // write ctx [B,S,D] (transpose back to (b, s, h*HD+d))
    const int b = bh >> 4;      // / NHEAD
    const int h = bh & 15;
#pragma unroll
    for (int i = 0; i < 4; ++i) {
        float inv = 1.f / l[i];
        int srow = q0 + r0 + i;
        float4 ov;
        ov.x = o[i][0]*inv; ov.y = o[i][1]*inv; ov.z = o[i][2]*inv; ov.w = o[i][3]*inv;
        *(float4*)&ctx[((size_t)(b*SEQ + srow))*DMODEL + h*HDIM + c0] = ov;
    }
}

// ---------------------------------------------------------------------------
// Launch
// ---------------------------------------------------------------------------
extern "C" void kernel_launch(void* const* d_in, const int* in_sizes, int n_in,
                              void* d_out, int out_size)
{
    const float* X  = (const float*)d_in[0];
    const float* Wq = (const float*)d_in[1];
    const float* bq = (const float*)d_in[2];
    const float* Wk = (const float*)d_in[3];
    const float* bk = (const float*)d_in[4];
    const float* Wv = (const float*)d_in[5];
    const float* bv = (const float*)d_in[6];
    const float* Wo = (const float*)d_in[7];
    const float* bo = (const float*)d_in[8];
    float* out = (float*)d_out;

    float *pq, *pk, *pv, *pctx;
    cudaGetSymbolAddress((void**)&pq,   g_q);
    cudaGetSymbolAddress((void**)&pk,   g_k);
    cudaGetSymbolAddress((void**)&pv,   g_v);
    cudaGetSymbolAddress((void**)&pctx, g_ctx);

    dim3 gg(DMODEL/BN, MTOT/BM);   // (8, 64)

    gemm_nt<1><<<gg, 256>>>(X, Wq, bq, pq, MTOT, DMODEL, DMODEL);
    gemm_nt<1><<<gg, 256>>>(X, Wk, bk, pk, MTOT, DMODEL, DMODEL);
    gemm_nt<1><<<gg, 256>>>(X, Wv, bv, pv, MTOT, DMODEL, DMODEL);

    int rope_n = BATCH*NHEAD*SEQ*(HDIM/2);
    rope_kernel<<<rope_n/256, 256>>>(pq, pk);

    int smem = (AQ*HDIM + 2*AK*HDIM + AQ*AK) * sizeof(float);  // 64 KB
    cudaFuncSetAttribute(attn_kernel, cudaFuncAttributeMaxDynamicSharedMemorySize, smem);
    attn_kernel<<<dim3(SEQ/AQ, BATCH*NHEAD), 256, smem>>>(pq, pk, pv, pctx);

    gemm_nt<0><<<gg, 256>>>(pctx, Wo, bo, out, MTOT, DMODEL, DMODEL);
}

// round 4
// speedup vs baseline: 5.1546x; 5.1546x over previous
#include <cuda_runtime.h>
#include <cuda_bf16.h>
#include <math.h>
#include <cstdint>

// Problem constants (fixed by the reference)
#define BATCH 4
#define SEQ   2048
#define DMODEL 1024
#define NHEAD 16
#define HDIM  64
#define MTOT  (BATCH*SEQ)

typedef __nv_bfloat16 bf16;

// ---------------------------------------------------------------------------
// Scratch (device globals)
// ---------------------------------------------------------------------------
__device__ float g_q[BATCH*NHEAD*SEQ*HDIM];   // [B,H,S,HD] f32
__device__ float g_k[BATCH*NHEAD*SEQ*HDIM];
__device__ float g_v[BATCH*NHEAD*SEQ*HDIM];
__device__ float g_ctx[MTOT*DMODEL];          // [B,S,D] f32

__device__ bf16 g_xhi[MTOT*DMODEL];
__device__ bf16 g_xlo[MTOT*DMODEL];
__device__ bf16 g_whi[4*DMODEL*DMODEL];       // packed Wq,Wk,Wv,Wo
__device__ bf16 g_wlo[4*DMODEL*DMODEL];
__device__ bf16 g_chi[MTOT*DMODEL];
__device__ bf16 g_clo[MTOT*DMODEL];

__device__ bf16 g_qhi[BATCH*NHEAD*SEQ*HDIM];  // post-rope splits
__device__ bf16 g_qlo[BATCH*NHEAD*SEQ*HDIM];
__device__ bf16 g_khi[BATCH*NHEAD*SEQ*HDIM];
__device__ bf16 g_klo[BATCH*NHEAD*SEQ*HDIM];
__device__ bf16 g_vhi[BATCH*NHEAD*SEQ*HDIM];
__device__ bf16 g_vlo[BATCH*NHEAD*SEQ*HDIM];

// ---------------------------------------------------------------------------
// Helpers
// ---------------------------------------------------------------------------
__device__ __forceinline__ uint32_t smem_u32(const void* p) {
    uint32_t a;
    asm("{ .reg .u64 t; cvta.to.shared.u64 t, %1; cvt.u32.u64 %0, t; }"
        : "=r"(a) : "l"(p));
    return a;
}
__device__ __forceinline__ void cp16(uint32_t dst, const void* src) {
    asm volatile("cp.async.cg.shared.global [%0], [%1], 16;" :: "r"(dst), "l"(src));
}
__device__ __forceinline__ void cp_commit() {
    asm volatile("cp.async.commit_group;" ::: "memory");
}
__device__ __forceinline__ void cp_wait1() {
    asm volatile("cp.async.wait_group 1;" ::: "memory");
}
__device__ __forceinline__ void ldsm4(uint32_t* r, uint32_t addr) {
    asm volatile("ldmatrix.sync.aligned.m8n8.x4.shared.b16 {%0,%1,%2,%3}, [%4];"
                 : "=r"(r[0]), "=r"(r[1]), "=r"(r[2]), "=r"(r[3]) : "r"(addr));
}
__device__ __forceinline__ void ldsm4t(uint32_t* r, uint32_t addr) {
    asm volatile("ldmatrix.sync.aligned.m8n8.x4.trans.shared.b16 {%0,%1,%2,%3}, [%4];"
                 : "=r"(r[0]), "=r"(r[1]), "=r"(r[2]), "=r"(r[3]) : "r"(addr));
}
__device__ __forceinline__ void mma_bf16(float* c, const uint32_t* a, const uint32_t* b) {
    asm volatile(
        "mma.sync.aligned.m16n8k16.row.col.f32.bf16.bf16.f32 "
        "{%0,%1,%2,%3}, {%4,%5,%6,%7}, {%8,%9}, {%0,%1,%2,%3};"
        : "+f"(c[0]), "+f"(c[1]), "+f"(c[2]), "+f"(c[3])
        : "r"(a[0]), "r"(a[1]), "r"(a[2]), "r"(a[3]), "r"(b[0]), "r"(b[1]));
}
__device__ __forceinline__ uint32_t pack_bf16(float lo, float hi) {
    uint32_t r;
    asm("cvt.rn.bf16x2.f32 %0, %1, %2;" : "=r"(r) : "f"(hi), "f"(lo));
    return r;
}

// ---------------------------------------------------------------------------
// fp32 -> bf16 hi/lo split
// ---------------------------------------------------------------------------
__global__ void split_kernel(const float* __restrict__ x,
                             bf16* __restrict__ hi, bf16* __restrict__ lo, int n4)
{
    int i = blockIdx.x * blockDim.x + threadIdx.x;
    if (i >= n4) return;
    float4 v = ((const float4*)x)[i];
    bf16 h0 = __float2bfloat16(v.x), h1 = __float2bfloat16(v.y);
    bf16 h2 = __float2bfloat16(v.z), h3 = __float2bfloat16(v.w);
    bf16 l0 = __float2bfloat16(v.x - __bfloat162float(h0));
    bf16 l1 = __float2bfloat16(v.y - __bfloat162float(h1));
    bf16 l2 = __float2bfloat16(v.z - __bfloat162float(h2));
    bf16 l3 = __float2bfloat16(v.w - __bfloat162float(h3));
    ((__nv_bfloat162*)hi)[2*i]   = __halves2bfloat162(h0, h1);
    ((__nv_bfloat162*)hi)[2*i+1] = __halves2bfloat162(h2, h3);
    ((__nv_bfloat162*)lo)[2*i]   = __halves2bfloat162(l0, l1);
    ((__nv_bfloat162*)lo)[2*i+1] = __halves2bfloat162(l2, l3);
}

// ---------------------------------------------------------------------------
// HMMA GEMM: C[m,n] = sum_k A[m,k]*W[n,k] + bias[n]  (bf16x3 split, f32 acc)
// Tiles: 128x128x32, 8 warps (2M x 4N), warp tile 64x32, double-buffered.
// MODE 0: row-major out. MODE 1: scatter to [B,H,S,HD], z selects q/k/v.
// ---------------------------------------------------------------------------
#define GSTRIDE 40                        // bf16 per smem row (32+8 pad)
#define GTILE_B (128*GSTRIDE*2)           // 10240 bytes per tile
#define GSTAGE_B (4*GTILE_B)              // Ahi,Alo,Bhi,Blo
#define GSMEM (2*GSTAGE_B)                // 81920

__device__ __forceinline__ void g_load_stage(
    uint32_t smb, int s, int kt, int m0, int n0,
    const bf16* Ah, const bf16* Al, const bf16* wh, const bf16* wl, int tid)
{
    uint32_t base = smb + s * GSTAGE_B;
    int kc = kt * 32;
#pragma unroll
    for (int i = 0; i < 8; ++i) {
        int t = tid + i * 256;
        int tile = t >> 9;
        int r = (t >> 2) & 127;
        int c = t & 3;                    // 4 x 16B = 64B = 32 bf16 row  (OK)
        const bf16* src;
        if      (tile == 0) src = Ah + (size_t)(m0 + r) * DMODEL + kc + c * 8;
        else if (tile == 1) src = Al + (size_t)(m0 + r) * DMODEL + kc + c * 8;
        else if (tile == 2) src = wh + (size_t)(n0 + r) * DMODEL + kc + c * 8;
        else                src = wl + (size_t)(n0 + r) * DMODEL + kc + c * 8;
        cp16(base + tile * GTILE_B + r * (GSTRIDE*2) + c * 16, src);
    }
    cp_commit();
}

template<int MODE>
__global__ void __launch_bounds__(256, 1)
gemm_hmma(const bf16* __restrict__ Ah, const bf16* __restrict__ Al,
          const bf16* __restrict__ Wh, const bf16* __restrict__ Wl,
          const float* __restrict__ b0, const float* __restrict__ b1,
          const float* __restrict__ b2,
          float* __restrict__ dq, float* __restrict__ dk, float* __restrict__ dv)
{
    extern __shared__ char smc[];
    const uint32_t smb = smem_u32(smc);
    const int tid  = threadIdx.x;
    const int warp = tid >> 5, lane = tid & 31;
    const int z  = blockIdx.z;
    const int m0 = blockIdx.y * 128;
    const int n0 = blockIdx.x * 128;
    const int wm = (warp & 1) * 64;
    const int wn = (warp >> 1) * 32;

    const bf16* wh = Wh + ((size_t)z << 20);
    const bf16* wl = Wl + ((size_t)z << 20);
    const float* bias = (z == 0) ? b0 : (z == 1) ? b1 : b2;
    float* dst        = (z == 0) ? dq : (z == 1) ? dk : dv;

    float acc[4][4][4];
#pragma unroll
    for (int i = 0; i < 4; ++i)
#pragma unroll
        for (int j = 0; j < 4; ++j)
#pragma unroll
            for (int c = 0; c < 4; ++c) acc[i][j][c] = 0.f;

    g_load_stage(smb, 0, 0, m0, n0, Ah, Al, wh, wl, tid);
    g_load_stage(smb, 1, 1, m0, n0, Ah, Al, wh, wl, tid);

    const int arow = lane & 15, akh = lane >> 4;
    const int brow = lane & 7, bkh = (lane >> 3) & 1, bpr = lane >> 4;

    for (int kt = 0; kt < 32; ++kt) {
        uint32_t base = smb + (kt & 1) * GSTAGE_B;
        cp_wait1();
        __syncthreads();

#pragma unroll
        for (int kk = 0; kk < 2; ++kk) {
            uint32_t ah[4][4], al[4][4];
#pragma unroll
            for (int mt = 0; mt < 4; ++mt) {
                uint32_t ad = base + (wm + mt*16 + arow) * (GSTRIDE*2)
                                   + (kk*16 + akh*8) * 2;
                ldsm4(ah[mt], ad);
                ldsm4(al[mt], ad + GTILE_B);
            }
            uint32_t bh[4][2], bl[4][2];
#pragma unroll
            for (int p = 0; p < 2; ++p) {
                uint32_t bd = base + 2*GTILE_B
                            + (wn + p*16 + bpr*8 + brow) * (GSTRIDE*2)
                            + (kk*16 + bkh*8) * 2;
                uint32_t r[4];
                ldsm4(r, bd);
                bh[2*p][0]=r[0]; bh[2*p][1]=r[1]; bh[2*p+1][0]=r[2]; bh[2*p+1][1]=r[3];
                ldsm4(r, bd + GTILE_B);
                bl[2*p][0]=r[0]; bl[2*p][1]=r[1]; bl[2*p+1][0]=r[2]; bl[2*p+1][1]=r[3];
            }
#pragma unroll
            for (int mt = 0; mt < 4; ++mt)
#pragma unroll
                for (int nt = 0; nt < 4; ++nt) {
                    mma_bf16(acc[mt][nt], ah[mt], bh[nt]);
                    mma_bf16(acc[mt][nt], ah[mt], bl[nt]);
                    mma_bf16(acc[mt][nt], al[mt], bh[nt]);
                }
        }
        __syncthreads();
        if (kt + 2 < 32) g_load_stage(smb, kt & 1, kt + 2, m0, n0, Ah, Al, wh, wl, tid);
        else             cp_commit();
    }

    // epilogue
    const int gid = lane >> 2, tig = lane & 3;
#pragma unroll
    for (int mt = 0; mt < 4; ++mt) {
#pragma unroll
        for (int nt = 0; nt < 4; ++nt) {
#pragma unroll
            for (int half = 0; half < 2; ++half) {
                int mrow = m0 + wm + mt*16 + gid + half*8;
                int ncol = n0 + wn + nt*8 + tig*2;
                float2 v;
                v.x = acc[mt][nt][half*2]   + bias[ncol];
                v.y = acc[mt][nt][half*2+1] + bias[ncol+1];
                if (MODE == 0) {
                    *(float2*)&dst[(size_t)mrow * DMODEL + ncol] = v;
                } else {
                    int h  = ncol >> 6, hd = ncol & 63;
                    int bb = mrow >> 11, s = mrow & (SEQ-1);
                    *(float2*)&dst[(((size_t)(bb*NHEAD + h))*SEQ + s)*HDIM + hd] = v;
                }
            }
        }
    }
}

// ---------------------------------------------------------------------------
// RoPE + split to bf16 hi/lo (reference: "c"=sin half, "s"=cos half)
// ---------------------------------------------------------------------------
__global__ void rope_split(const float* __restrict__ q, const float* __restrict__ k,
                           bf16* __restrict__ qhi, bf16* __restrict__ qlo,
                           bf16* __restrict__ khi, bf16* __restrict__ klo)
{
    int idx = blockIdx.x*blockDim.x + threadIdx.x;
    if (idx >= BATCH*NHEAD*SEQ*(HDIM/2)) return;
    int j  = idx & 31;
    int s  = (idx >> 5) & (SEQ-1);
    int bh = idx >> 16;

    float inv = powf(10000.f, -(float)j / 32.f);
    float ang = (float)s * inv;
    float sn, cs;
    sincosf(ang, &sn, &cs);

    size_t base = ((size_t)bh*SEQ + s)*HDIM;
    {
        float x1 = q[base+j], x2 = q[base+j+32];
        float y1 = x1*sn - x2*cs, y2 = x2*sn + x1*cs;
        bf16 h1 = __float2bfloat16(y1), h2 = __float2bfloat16(y2);
        qhi[base+j] = h1; qhi[base+j+32] = h2;
        qlo[base+j]    = __float2bfloat16(y1 - __bfloat162float(h1));
        qlo[base+j+32] = __float2bfloat16(y2 - __bfloat162float(h2));
    }
    {
        float x1 = k[base+j], x2 = k[base+j+32];
        float y1 = x1*sn - x2*cs, y2 = x2*sn + x1*cs;
        bf16 h1 = __float2bfloat16(y1), h2 = __float2bfloat16(y2);
        khi[base+j] = h1; khi[base+j+32] = h2;
        klo[base+j]    = __float2bfloat16(y1 - __bfloat162float(h1));
        klo[base+j+32] = __float2bfloat16(y2 - __bfloat162float(h2));
    }
}

// ---------------------------------------------------------------------------
// Flash attention on HMMA, bf16x3. 64-row Q tiles, 4 warps (16 rows each),
// double-buffered K/V (hi/lo) tiles of 64x64.
// ---------------------------------------------------------------------------
#define ASTRIDE 72                    // bf16 per smem row (64+8 pad)
#define ATILE_B (64*ASTRIDE*2)        // 9216 bytes
#define ASMEM (2*ATILE_B + 8*ATILE_B) // Qhi,Qlo + 2 stages x (Khi,Klo,Vhi,Vlo)

__device__ __forceinline__ void a_load_kv(
    uint32_t smb, int s, int k0, const bf16* kh, const bf16* kl,
    const bf16* vh, const bf16* vl, int tid)
{
    uint32_t base = smb + 2*ATILE_B + s * 4*ATILE_B;
    // 4 tiles x 64 rows x 8 chunks (128B/row) = 2048 transfers
#pragma unroll
    for (int i = 0; i < 16; ++i) {
        int t = tid + i * 128;
        int tile = t >> 9;
        int r = (t >> 3) & 63;
        int c = t & 7;
        const bf16* src;
        if      (tile == 0) src = kh + (size_t)(k0 + r) * HDIM + c * 8;
        else if (tile == 1) src = kl + (size_t)(k0 + r) * HDIM + c * 8;
        else if (tile == 2) src = vh + (size_t)(k0 + r) * HDIM + c * 8;
        else                src = vl + (size_t)(k0 + r) * HDIM + c * 8;
        cp16(base + tile * ATILE_B + r * (ASTRIDE*2) + c * 16, src);
    }
    cp_commit();
}

__global__ void __launch_bounds__(128)
attn_hmma(const bf16* __restrict__ Qh, const bf16* __restrict__ Ql,
          const bf16* __restrict__ Kh, const bf16* __restrict__ Kl,
          const bf16* __restrict__ Vh, const bf16* __restrict__ Vl,
          float* __restrict__ ctx)
{
    extern __shared__ char smc[];
    const uint32_t smb = smem_u32(smc);
    const int tid = threadIdx.x;
    const int warp = tid >> 5, lane = tid & 31;
    const int q0 = blockIdx.x * 64;
    const int bh = blockIdx.y;

    const bf16* qhg = Qh + ((size_t)bh*SEQ + q0)*HDIM;
    const bf16* qlg = Ql + ((size_t)bh*SEQ + q0)*HDIM;
    const bf16* khg = Kh + (size_t)bh*SEQ*HDIM;
    const bf16* klg = Kl + (size_t)bh*SEQ*HDIM;
    const bf16* vhg = Vh + (size_t)bh*SEQ*HDIM;
    const bf16* vlg = Vl + (size_t)bh*SEQ*HDIM;

    // Q tiles (2 tiles x 64 rows x 8 chunks = 1024 transfers) + first KV stage
#pragma unroll
    for (int i = 0; i < 8; ++i) {
        int t = tid + i * 128;
        int tile = t >> 9;            // 0: hi, 1: lo
        int r = (t >> 3) & 63;
        int c = t & 7;
        const bf16* src = (tile ? qlg : qhg) + (size_t)r * HDIM + c * 8;
        cp16(smb + tile * ATILE_B + r * (ASTRIDE*2) + c * 16, src);
    }
    a_load_kv(smb, 0, 0, khg, klg, vhg, vlg, tid);   // commits group (Q + stage0)
    a_load_kv(smb, 1, 64, khg, klg, vhg, vlg, tid);

    const int gid = lane >> 2, tig = lane & 3;
    const int arow = lane & 15, akh = lane >> 4;
    const int brow = lane & 7, bkh = (lane >> 3) & 1, bpr = lane >> 4;

    uint32_t qh[4][4], ql[4][4];
    float o[8][4];
#pragma unroll
    for (int nt = 0; nt < 8; ++nt)
#pragma unroll
        for (int c = 0; c < 4; ++c) o[nt][c] = 0.f;
    float mrow0 = -INFINITY, mrow1 = -INFINITY, lrow0 = 0.f, lrow1 = 0.f;

    for (int kt = 0; kt < SEQ/64; ++kt) {
        uint32_t base = smb + 2*ATILE_B + (kt & 1) * 4*ATILE_B;
        cp_wait1();
        __syncthreads();

        if (kt == 0) {
            // load Q fragments once
#pragma unroll
            for (int kx = 0; kx < 4; ++kx) {
                uint32_t ad = smb + (warp*16 + arow) * (ASTRIDE*2) + (kx*16 + akh*8) * 2;
                ldsm4(qh[kx], ad);
                ldsm4(ql[kx], ad + ATILE_B);
            }
        }

        // S = Q K^T  (bf16x3)
        float s[8][4];
#pragma unroll
        for (int nt = 0; nt < 8; ++nt)
#pragma unroll
            for (int c = 0; c < 4; ++c) s[nt][c] = 0.f;

#pragma unroll
        for (int kx = 0; kx < 4; ++kx) {
            uint32_t kbh[8][2], kbl[8][2];
#pragma unroll
            for (int p = 0; p < 4; ++p) {
                uint32_t bd = base + (p*16 + bpr*8 + brow) * (ASTRIDE*2)
                            + (kx*16 + bkh*8) * 2;
                uint32_t r[4];
                ldsm4(r, bd);
                kbh[2*p][0]=r[0]; kbh[2*p][1]=r[1]; kbh[2*p+1][0]=r[2]; kbh[2*p+1][1]=r[3];
                ldsm4(r, bd + ATILE_B);
                kbl[2*p][0]=r[0]; kbl[2*p][1]=r[1]; kbl[2*p+1][0]=r[2]; kbl[2*p+1][1]=r[3];
            }
#pragma unroll
            for (int nt = 0; nt < 8; ++nt) {
                mma_bf16(s[nt], qh[kx], kbh[nt]);
                mma_bf16(s[nt], qh[kx], kbl[nt]);
                mma_bf16(s[nt], ql[kx], kbh[nt]);
            }
        }

        // online softmax (scale 1/8); rows gid (c0,c1) and gid+8 (c2,c3)
        float mx0 = -INFINITY, mx1 = -INFINITY;
#pragma unroll
        for (int nt = 0; nt < 8; ++nt) {
#pragma unroll
            for (int c = 0; c < 4; ++c) s[nt][c] *= 0.125f;
            mx0 = fmaxf(mx0, fmaxf(s[nt][0], s[nt][1]));
            mx1 = fmaxf(mx1, fmaxf(s[nt][2], s[nt][3]));
        }
        mx0 = fmaxf(mx0, __shfl_xor_sync(0xffffffffu, mx0, 1));
        mx0 = fmaxf(mx0, __shfl_xor_sync(0xffffffffu, mx0, 2));
        mx1 = fmaxf(mx1, __shfl_xor_sync(0xffffffffu, mx1, 1));
        mx1 = fmaxf(mx1, __shfl_xor_sync(0xffffffffu, mx1, 2));
        float mn0 = fmaxf(mrow0, mx0), mn1 = fmaxf(mrow1, mx1);
        float al0 = __expf(mrow0 - mn0), al1 = __expf(mrow1 - mn1);
        mrow0 = mn0; mrow1 = mn1;

        float ls0 = 0.f, ls1 = 0.f;
#pragma unroll
        for (int nt = 0; nt < 8; ++nt) {
            s[nt][0] = __expf(s[nt][0] - mn0);
            s[nt][1] = __expf(s[nt][1] - mn0);
            s[nt][2] = __expf(s[nt][2] - mn1);
            s[nt][3] = __expf(s[nt][3] - mn1);
            ls0 += s[nt][0] + s[nt][1];
            ls1 += s[nt][2] + s[nt][3];
        }
        ls0 += __shfl_xor_sync(0xffffffffu, ls0, 1);
        ls0 += __shfl_xor_sync(0xffffffffu, ls0, 2);
        ls1 += __shfl_xor_sync(0xffffffffu, ls1, 1);
        ls1 += __shfl_xor_sync(0xffffffffu, ls1, 2);
        lrow0 = lrow0 * al0 + ls0;
        lrow1 = lrow1 * al1 + ls1;

#pragma unroll
        for (int nt = 0; nt < 8; ++nt) {
            o[nt][0] *= al0; o[nt][1] *= al0;
            o[nt][2] *= al1; o[nt][3] *= al1;
        }

        // pack P into A-fragments (hi + residual lo)
        uint32_t ahi[4][4], alo[4][4];
#pragma unroll
        for (int j = 0; j < 4; ++j) {
#pragma unroll
            for (int rr = 0; rr < 4; ++rr) {
                int nt = 2*j + (rr >> 1);
                float p0 = s[nt][(rr & 1)*2], p1 = s[nt][(rr & 1)*2 + 1];
                uint32_t hpack = pack_bf16(p0, p1);
                ahi[j][rr] = hpack;
                __nv_bfloat162 hp = *(__nv_bfloat162*)&hpack;
                alo[j][rr] = pack_bf16(p0 - __bfloat162float(hp.x),
                                       p1 - __bfloat162float(hp.y));
            }
        }

        // O += P V
#pragma unroll
        for (int j = 0; j < 4; ++j) {
            uint32_t vbh[8][2], vbl[8][2];
#pragma unroll
            for (int p = 0; p < 4; ++p) {
                uint32_t vd = base + 2*ATILE_B
                            + (j*16 + (lane & 15)) * (ASTRIDE*2)
                            + (p*16 + (lane >> 4)*8) * 2;
                uint32_t r[4];
                ldsm4t(r, vd);
                vbh[2*p][0]=r[0]; vbh[2*p][1]=r[1]; vbh[2*p+1][0]=r[2]; vbh[2*p+1][1]=r[3];
                ldsm4t(r, vd + ATILE_B);
                vbl[2*p][0]=r[0]; vbl[2*p][1]=r[1]; vbl[2*p+1][0]=r[2]; vbl[2*p+1][1]=r[3];
            }
#pragma unroll
            for (int nt = 0; nt < 8; ++nt) {
                mma_bf16(o[nt], ahi[j], vbh[nt]);
                mma_bf16(o[nt], ahi[j], vbl[nt]);
                mma_bf16(o[nt], alo[j], vbh[nt]);
            }
        }

        __syncthreads();
        if (kt + 2 < SEQ/64) a_load_kv(smb, kt & 1, (kt+2)*64, khg, klg, vhg, vlg, tid);
        else                 cp_commit();
    }

    // write ctx
    const int b = bh >> 4, h = bh & 15;
    float il0 = 1.f / lrow0, il1 = 1.f / lrow1;
    int r0g = q0 + warp*16 + gid;
#pragma unroll
    for (int nt = 0; nt < 8; ++nt) {
        int col = h*HDIM + nt*8 + tig*2;
        float2 v0; v0.x = o[nt][0]*il0; v0.y = o[nt][1]*il0;
        float2 v1; v1.x = o[nt][2]*il1; v1.y = o[nt][3]*il1;
        *(float2*)&ctx[((size_t)(b*SEQ + r0g))*DMODEL + col] = v0;
        *(float2*)&ctx[((size_t)(b*SEQ + r0g + 8))*DMODEL + col] = v1;
    }
}

// ---------------------------------------------------------------------------
// Launch
// ---------------------------------------------------------------------------
extern "C" void kernel_launch(void* const* d_in, const int* in_sizes, int n_in,
                              void* d_out, int out_size)
{
    const float* X  = (const float*)d_in[0];
    const float* Wq = (const float*)d_in[1];
    const float* bq = (const float*)d_in[2];
    const float* Wk = (const float*)d_in[3];
    const float* bk = (const float*)d_in[4];
    const float* Wv = (const float*)d_in[5];
    const float* bv = (const float*)d_in[6];
    const float* Wo = (const float*)d_in[7];
    const float* bo = (const float*)d_in[8];
    float* out = (float*)d_out;

    float *pq, *pk, *pv, *pctx;
    bf16 *xhi, *xlo, *whi, *wlo, *chi, *clo;
    bf16 *qhi, *qlo, *khi, *klo, *vhi, *vlo;
    cudaGetSymbolAddress((void**)&pq,   g_q);
    cudaGetSymbolAddress((void**)&pk,   g_k);
    cudaGetSymbolAddress((void**)&pv,   g_v);
    cudaGetSymbolAddress((void**)&pctx, g_ctx);
    cudaGetSymbolAddress((void**)&xhi,  g_xhi);
    cudaGetSymbolAddress((void**)&xlo,  g_xlo);
    cudaGetSymbolAddress((void**)&whi,  g_whi);
    cudaGetSymbolAddress((void**)&wlo,  g_wlo);
    cudaGetSymbolAddress((void**)&chi,  g_chi);
    cudaGetSymbolAddress((void**)&clo,  g_clo);
    cudaGetSymbolAddress((void**)&qhi,  g_qhi);
    cudaGetSymbolAddress((void**)&qlo,  g_qlo);
    cudaGetSymbolAddress((void**)&khi,  g_khi);
    cudaGetSymbolAddress((void**)&klo,  g_klo);
    cudaGetSymbolAddress((void**)&vhi,  g_vhi);
    cudaGetSymbolAddress((void**)&vlo,  g_vlo);

    cudaFuncSetAttribute(gemm_hmma<0>, cudaFuncAttributeMaxDynamicSharedMemorySize, GSMEM);
    cudaFuncSetAttribute(gemm_hmma<1>, cudaFuncAttributeMaxDynamicSharedMemorySize, GSMEM);
    cudaFuncSetAttribute(attn_hmma, cudaFuncAttributeMaxDynamicSharedMemorySize, ASMEM);

    // splits
    split_kernel<<<(MTOT*DMODEL/4)/256, 256>>>(X, xhi, xlo, MTOT*DMODEL/4);
    split_kernel<<<(DMODEL*DMODEL/4)/256, 256>>>(Wq, whi + 0*1048576, wlo + 0*1048576, DMODEL*DMODEL/4);
    split_kernel<<<(DMODEL*DMODEL/4)/256, 256>>>(Wk, whi + 1*1048576, wlo + 1*1048576, DMODEL*DMODEL/4);
    split_kernel<<<(DMODEL*DMODEL/4)/256, 256>>>(Wv, whi + 2*1048576, wlo + 2*1048576, DMODEL*DMODEL/4);
    split_kernel<<<(DMODEL*DMODEL/4)/256, 256>>>(Wo, whi + 3*1048576, wlo + 3*1048576, DMODEL*DMODEL/4);

    // fused QKV projection (z = 0/1/2)
    gemm_hmma<1><<<dim3(DMODEL/128, MTOT/128, 3), 256, GSMEM>>>(
        xhi, xlo, whi, wlo, bq, bk, bv, pq, pk, pv);

    // rope + split q/k, split v
    rope_split<<<(BATCH*NHEAD*SEQ*(HDIM/2))/256, 256>>>(pq, pk, qhi, qlo, khi, klo);
    split_kernel<<<(BATCH*NHEAD*SEQ*HDIM/4)/256, 256>>>(pv, vhi, vlo, BATCH*NHEAD*SEQ*HDIM/4);

    // attention
    attn_hmma<<<dim3(SEQ/64, BATCH*NHEAD), 128, ASMEM>>>(
        qhi, qlo, khi, klo, vhi, vlo, pctx);

    // output projection
    split_kernel<<<(MTOT*DMODEL/4)/256, 256>>>(pctx, chi, clo, MTOT*DMODEL/4);
    gemm_hmma<0><<<dim3(DMODEL/128, MTOT/128, 1), 256, GSMEM>>>(
        chi, clo, whi + 3*1048576, wlo + 3*1048576, bo, bo, bo, out, out, out);
}